// round 10
// baseline (speedup 1.0000x reference)
#include <cuda_runtime.h>
#include <cuda_bf16.h>
#include <stdint.h>
#include <math.h>

#define B_  2
#define T_  2048
#define D_  2048
#define H_  32
#define HD_ 64
#define M_  (B_ * T_)          // 4096 rows for all GEMMs
#define MD_ ((size_t)M_ * D_)

// ---------------------------------------------------------------------------
// Scratch (device globals — no allocation allowed). ~144 MB total.
// (Empirically: runs with >=176 MB of static globals have failed to launch;
//  all passing runs were <=151 MB. Stay at the R7-passing footprint.)
// ---------------------------------------------------------------------------
__device__ __nv_bfloat16 g_qhi[MD_];   // [bh][t][hd] head-split
__device__ __nv_bfloat16 g_qlo[MD_];
__device__ __nv_bfloat16 g_khi[MD_];
__device__ __nv_bfloat16 g_klo[MD_];
__device__ __nv_bfloat16 g_vhi[MD_];
__device__ __nv_bfloat16 g_vlo[MD_];
__device__ __nv_bfloat16 g_xhi[MD_];   // X, later ctx
__device__ __nv_bfloat16 g_xlo[MD_];
__device__ __nv_bfloat16 g_whi[(size_t)D_ * D_];   // one weight at a time
__device__ __nv_bfloat16 g_wlo[(size_t)D_ * D_];

// ---------------------------------------------------------------------------
// PTX helpers (plain sm_80-era; nothing 'a'-gated)
// ---------------------------------------------------------------------------
__device__ __forceinline__ uint32_t smem_u32(const void* p) {
    uint32_t a;
    asm("{ .reg .u64 t; cvta.to.shared.u64 t, %1; cvt.u32.u64 %0, t; }"
        : "=r"(a) : "l"(p));
    return a;
}
#define CP_ASYNC16(dst, src) \
    asm volatile("cp.async.cg.shared.global [%0], [%1], 16;" \
                 :: "r"(dst), "l"(src))
#define CP_COMMIT  asm volatile("cp.async.commit_group;" ::: "memory")
#define CP_WAIT(n) asm volatile("cp.async.wait_group %0;" :: "n"(n) : "memory")

__device__ __forceinline__ void ldm_x4(uint32_t (&r)[4], uint32_t addr) {
    asm volatile("ldmatrix.sync.aligned.m8n8.x4.shared.b16 {%0,%1,%2,%3}, [%4];"
                 : "=r"(r[0]), "=r"(r[1]), "=r"(r[2]), "=r"(r[3]) : "r"(addr));
}
__device__ __forceinline__ void ldm_x4_t(uint32_t (&r)[4], uint32_t addr) {
    asm volatile("ldmatrix.sync.aligned.m8n8.x4.trans.shared.b16 {%0,%1,%2,%3}, [%4];"
                 : "=r"(r[0]), "=r"(r[1]), "=r"(r[2]), "=r"(r[3]) : "r"(addr));
}
__device__ __forceinline__ void mma16816(float (&d)[4], const uint32_t (&a)[4],
                                         uint32_t b0, uint32_t b1) {
    asm volatile(
        "mma.sync.aligned.m16n8k16.row.col.f32.bf16.bf16.f32 "
        "{%0,%1,%2,%3},{%4,%5,%6,%7},{%8,%9},{%0,%1,%2,%3};"
        : "+f"(d[0]), "+f"(d[1]), "+f"(d[2]), "+f"(d[3])
        : "r"(a[0]), "r"(a[1]), "r"(a[2]), "r"(a[3]), "r"(b0), "r"(b1));
}
__device__ __forceinline__ uint32_t pack_bf16x2(__nv_bfloat16 lo, __nv_bfloat16 hi) {
    __nv_bfloat162 v(lo, hi);
    return *reinterpret_cast<uint32_t*>(&v);
}
__device__ __forceinline__ void split2(float a, float b, uint32_t& hi, uint32_t& lo) {
    __nv_bfloat16 ha = __float2bfloat16_rn(a);
    __nv_bfloat16 hb = __float2bfloat16_rn(b);
    hi = pack_bf16x2(ha, hb);
    lo = pack_bf16x2(__float2bfloat16_rn(a - __bfloat162float(ha)),
                     __float2bfloat16_rn(b - __bfloat162float(hb)));
}

// ---------------------------------------------------------------------------
// fp32 -> (hi, lo) bf16 split, elementwise. 1 float4 per thread.
// ---------------------------------------------------------------------------
__global__ __launch_bounds__(256) void conv_split(
    const float4* __restrict__ src,
    uint2* __restrict__ hi, uint2* __restrict__ lo, int n4)
{
    int i = blockIdx.x * 256 + threadIdx.x;
    if (i >= n4) return;
    float4 f = src[i];
    uint2 h, l;
    split2(f.x, f.y, h.x, l.x);
    split2(f.z, f.w, h.y, l.y);
    hi[i] = h;
    lo[i] = l;
}

// ---------------------------------------------------------------------------
// Tensor-core GEMM via mma.sync (bf16 hi/lo 3-term split), TERM-MAJOR ILP:
//   C[m][n] = sum_k A[m][k]*W[n][k] + bias[n]
// CTA 128x128, BK=32, 256 thr (8 warps, warp tile 32x64).
// MODE 0: fp32 [m][n] to outf.  MODE 1: head-split bf16 hi/lo to outh/outl.
// ---------------------------------------------------------------------------
#define TILE_B   10240         // bytes per 128x32 tile (stride-40 rows)
#define STAGE_B  40960
#define GSMEM    (2 * STAGE_B) // 81920 B

template <int MODE>
__global__ __launch_bounds__(256, 2) void gemm_mma(
    const __nv_bfloat16* __restrict__ Ahi,
    const __nv_bfloat16* __restrict__ Alo,
    const __nv_bfloat16* __restrict__ Whi,
    const __nv_bfloat16* __restrict__ Wlo,
    const float* __restrict__ bias,
    float* __restrict__ outf,
    __nv_bfloat16* __restrict__ outh,
    __nv_bfloat16* __restrict__ outl)
{
    extern __shared__ __nv_bfloat16 sm[];
    const uint32_t sbase = smem_u32(sm);

    const int tid  = threadIdx.x;
    const int lane = tid & 31;
    const int wid  = tid >> 5;
    const int wm   = wid & 3;
    const int wn   = wid >> 2;
    const int m0   = blockIdx.y * 128;
    const int n0   = blockIdx.x * 128;

    float acc[2][8][4];
#pragma unroll
    for (int mt = 0; mt < 2; mt++)
#pragma unroll
        for (int nt = 0; nt < 8; nt++)
#pragma unroll
            for (int e = 0; e < 4; e++) acc[mt][nt][e] = 0.0f;

    auto load_stage = [&](int s, int k0) {
        const uint32_t st = sbase + (uint32_t)s * STAGE_B;
#pragma unroll
        for (int t8 = 0; t8 < 8; t8++) {
            int c    = tid + t8 * 256;
            int tile = c >> 9;
            int rem  = c & 511;
            int r    = rem >> 2;
            int kc   = (rem & 3) * 8;
            uint32_t dst = st + (uint32_t)tile * TILE_B + (uint32_t)(r * 40 + kc) * 2;
            const __nv_bfloat16* g;
            if (tile == 0)      g = Ahi + (size_t)(m0 + r) * 2048 + k0 + kc;
            else if (tile == 1) g = Alo + (size_t)(m0 + r) * 2048 + k0 + kc;
            else if (tile == 2) g = Whi + (size_t)(n0 + r) * 2048 + k0 + kc;
            else                g = Wlo + (size_t)(n0 + r) * 2048 + k0 + kc;
            CP_ASYNC16(dst, g);
        }
    };

    load_stage(0, 0);
    CP_COMMIT;

    const int NIT = 2048 / 32;

    for (int it = 0; it < NIT; it++) {
        const int s = it & 1;
        if (it + 1 < NIT) {
            load_stage(s ^ 1, (it + 1) * 32);
            CP_COMMIT;
            CP_WAIT(1);
        } else {
            CP_WAIT(0);
        }
        __syncthreads();

        const uint32_t st = sbase + (uint32_t)s * STAGE_B;
#pragma unroll
        for (int ks = 0; ks < 2; ks++) {
            uint32_t aHi[2][4], aLo[2][4];
            const int arow = lane & 15;
            const int akof = ks * 16 + ((lane >> 4) << 3);
#pragma unroll
            for (int mt = 0; mt < 2; mt++) {
                uint32_t ad = st + (uint32_t)((wm * 32 + mt * 16 + arow) * 40 + akof) * 2;
                ldm_x4(aHi[mt], ad);
                ldm_x4(aLo[mt], ad + TILE_B);
            }
            const int brow = (lane & 7) + ((lane >> 4) << 3);
            const int bkof = ks * 16 + (((lane >> 3) & 1) << 3);
            // nt2-pairs, term-major: 8 independent acc chains per term group
#pragma unroll
            for (int pr = 0; pr < 2; pr++) {
                uint32_t bHi[2][4], bLo[2][4];
#pragma unroll
                for (int q = 0; q < 2; q++) {
                    int nt2 = pr * 2 + q;
                    uint32_t bd = st + 2 * TILE_B +
                        (uint32_t)((wn * 64 + nt2 * 16 + brow) * 40 + bkof) * 2;
                    ldm_x4(bHi[q], bd);
                    ldm_x4(bLo[q], bd + TILE_B);
                }
#pragma unroll
                for (int q = 0; q < 2; q++) {   // term 1: aHi * bHi
                    int nt2 = pr * 2 + q;
                    mma16816(acc[0][2 * nt2],     aHi[0], bHi[q][0], bHi[q][1]);
                    mma16816(acc[0][2 * nt2 + 1], aHi[0], bHi[q][2], bHi[q][3]);
                    mma16816(acc[1][2 * nt2],     aHi[1], bHi[q][0], bHi[q][1]);
                    mma16816(acc[1][2 * nt2 + 1], aHi[1], bHi[q][2], bHi[q][3]);
                }
#pragma unroll
                for (int q = 0; q < 2; q++) {   // term 2: aHi * bLo
                    int nt2 = pr * 2 + q;
                    mma16816(acc[0][2 * nt2],     aHi[0], bLo[q][0], bLo[q][1]);
                    mma16816(acc[0][2 * nt2 + 1], aHi[0], bLo[q][2], bLo[q][3]);
                    mma16816(acc[1][2 * nt2],     aHi[1], bLo[q][0], bLo[q][1]);
                    mma16816(acc[1][2 * nt2 + 1], aHi[1], bLo[q][2], bLo[q][3]);
                }
#pragma unroll
                for (int q = 0; q < 2; q++) {   // term 3: aLo * bHi
                    int nt2 = pr * 2 + q;
                    mma16816(acc[0][2 * nt2],     aLo[0], bHi[q][0], bHi[q][1]);
                    mma16816(acc[0][2 * nt2 + 1], aLo[0], bHi[q][2], bHi[q][3]);
                    mma16816(acc[1][2 * nt2],     aLo[1], bHi[q][0], bHi[q][1]);
                    mma16816(acc[1][2 * nt2 + 1], aLo[1], bHi[q][2], bHi[q][3]);
                }
            }
        }
        __syncthreads();
    }

    // ---- epilogue ----
    const int gr = lane >> 2;
    const int c2 = (lane & 3) * 2;
#pragma unroll
    for (int mt = 0; mt < 2; mt++) {
#pragma unroll
        for (int nt = 0; nt < 8; nt++) {
            int m = m0 + wm * 32 + mt * 16 + gr;
            int n = n0 + wn * 64 + nt * 8 + c2;
            float b0 = bias[n], b1 = bias[n + 1];
            float f00 = acc[mt][nt][0] + b0, f01 = acc[mt][nt][1] + b1;
            float f10 = acc[mt][nt][2] + b0, f11 = acc[mt][nt][3] + b1;
            if (MODE == 1) {
                int b  = m >> 11, t = m & (T_ - 1);
                int h  = n >> 6,  hd = n & (HD_ - 1);
                size_t i0 = (((size_t)(b * H_ + h)) * T_ + t) * HD_ + hd;
                size_t i1 = (((size_t)(b * H_ + h)) * T_ + (t + 8)) * HD_ + hd;
                uint32_t hi0, lo0, hi1, lo1;
                split2(f00, f01, hi0, lo0);
                split2(f10, f11, hi1, lo1);
                *reinterpret_cast<uint32_t*>(&outh[i0]) = hi0;
                *reinterpret_cast<uint32_t*>(&outl[i0]) = lo0;
                *reinterpret_cast<uint32_t*>(&outh[i1]) = hi1;
                *reinterpret_cast<uint32_t*>(&outl[i1]) = lo1;
            } else {
                *reinterpret_cast<float2*>(&outf[(size_t)m * D_ + n])
                    = make_float2(f00, f01);
                *reinterpret_cast<float2*>(&outf[(size_t)(m + 8) * D_ + n])
                    = make_float2(f10, f11);
            }
        }
    }
}

// ---------------------------------------------------------------------------
// Flash attention (causal) on tensor cores — FA2-style, TERM-MAJOR ILP.
// Grid (32, 64), 128 thr (4 warps). Br=Bc=64, HD=64.
// ---------------------------------------------------------------------------
#define FS        72                      // smem row stride (bf16)
#define FKTILE_B  (64 * FS * 2)           // 9216 B per 64x64 tile
#define FQ_B      (2 * FKTILE_B)
#define FSTG_B    (4 * FKTILE_B)
#define FSMEM     (FQ_B + 2 * FSTG_B)     // 92160 B

__global__ __launch_bounds__(128, 2) void flash_mma(
    const __nv_bfloat16* __restrict__ qhi_g, const __nv_bfloat16* __restrict__ qlo_g,
    const __nv_bfloat16* __restrict__ khi_g, const __nv_bfloat16* __restrict__ klo_g,
    const __nv_bfloat16* __restrict__ vhi_g, const __nv_bfloat16* __restrict__ vlo_g,
    __nv_bfloat16* __restrict__ chi, __nv_bfloat16* __restrict__ clo)
{
    extern __shared__ char fsm[];
    const uint32_t sb = smem_u32(fsm);
    const int tid  = threadIdx.x;
    const int lane = tid & 31;
    const int w    = tid >> 5;
    const int bh   = blockIdx.y;
    const int q0   = (gridDim.x - 1 - blockIdx.x) * 64;   // heavy tiles first
    const size_t hb = (size_t)bh * T_ * HD_;

#pragma unroll
    for (int m = 0; m < 2; m++) {
        const __nv_bfloat16* src = m ? qlo_g : qhi_g;
        uint32_t dstb = sb + (uint32_t)m * FKTILE_B;
#pragma unroll
        for (int i = 0; i < 4; i++) {
            int c = tid + i * 128;
            int r = c >> 3, ch = (c & 7) * 8;
            CP_ASYNC16(dstb + (uint32_t)(r * FS + ch) * 2,
                       src + hb + (size_t)(q0 + r) * HD_ + ch);
        }
    }
    CP_COMMIT;

    auto load_kv = [&](int s, int k0) {
        uint32_t st = sb + FQ_B + (uint32_t)s * FSTG_B;
        const __nv_bfloat16* srcs[4] = {khi_g, klo_g, vhi_g, vlo_g};
#pragma unroll
        for (int m = 0; m < 4; m++) {
#pragma unroll
            for (int i = 0; i < 4; i++) {
                int c = tid + i * 128;
                int r = c >> 3, ch = (c & 7) * 8;
                CP_ASYNC16(st + (uint32_t)m * FKTILE_B + (uint32_t)(r * FS + ch) * 2,
                           srcs[m] + hb + (size_t)(k0 + r) * HD_ + ch);
            }
        }
    };
    load_kv(0, 0);
    CP_COMMIT;
    CP_WAIT(1);
    __syncthreads();

    uint32_t qh[4][4], ql[4][4];
    {
        int arow = lane & 15, akof = (lane >> 4) * 8;
#pragma unroll
        for (int kt = 0; kt < 4; kt++) {
            uint32_t ad = sb + (uint32_t)((16 * w + arow) * FS + kt * 16 + akof) * 2;
            ldm_x4(qh[kt], ad);
            ldm_x4(ql[kt], ad + FKTILE_B);
        }
    }

    float ctx[8][4];
#pragma unroll
    for (int nt = 0; nt < 8; nt++)
#pragma unroll
        for (int e = 0; e < 4; e++) ctx[nt][e] = 0.0f;
    float mrow0 = -1e30f, mrow1 = -1e30f, lrow0 = 0.0f, lrow1 = 0.0f;

    const int nkv = (q0 >> 6) + 1;
    const int gr  = lane >> 2;
    const int c2  = (lane & 3) * 2;
    const float scale = 0.125f;
    const int qg0 = q0 + 16 * w + gr;
    const int qg1 = qg0 + 8;

    for (int kt = 0; kt < nkv; kt++) {
        const int s = kt & 1;
        if (kt + 1 < nkv) {
            load_kv(s ^ 1, (kt + 1) * 64);
            CP_COMMIT;
            CP_WAIT(1);
        } else {
            CP_WAIT(0);
        }
        __syncthreads();
        const uint32_t st = sb + FQ_B + (uint32_t)s * FSTG_B;

        // ---- S = Q K^T (3-term, term-major over all 4 nt2) ----
        float sa[8][4];
#pragma unroll
        for (int nt = 0; nt < 8; nt++)
#pragma unroll
            for (int e = 0; e < 4; e++) sa[nt][e] = 0.0f;
        {
            const int brow = (lane & 7) + ((lane >> 4) << 3);
            const int bkof = ((lane >> 3) & 1) << 3;
#pragma unroll
            for (int k4 = 0; k4 < 4; k4++) {
                uint32_t bh4[4][4], bl4[4][4];
#pragma unroll
                for (int nt2 = 0; nt2 < 4; nt2++) {
                    uint32_t bd = st +
                        (uint32_t)((nt2 * 16 + brow) * FS + k4 * 16 + bkof) * 2;
                    ldm_x4(bh4[nt2], bd);
                    ldm_x4(bl4[nt2], bd + FKTILE_B);
                }
#pragma unroll
                for (int nt2 = 0; nt2 < 4; nt2++) {
                    mma16816(sa[2 * nt2],     qh[k4], bh4[nt2][0], bh4[nt2][1]);
                    mma16816(sa[2 * nt2 + 1], qh[k4], bh4[nt2][2], bh4[nt2][3]);
                }
#pragma unroll
                for (int nt2 = 0; nt2 < 4; nt2++) {
                    mma16816(sa[2 * nt2],     qh[k4], bl4[nt2][0], bl4[nt2][1]);
                    mma16816(sa[2 * nt2 + 1], qh[k4], bl4[nt2][2], bl4[nt2][3]);
                }
#pragma unroll
                for (int nt2 = 0; nt2 < 4; nt2++) {
                    mma16816(sa[2 * nt2],     ql[k4], bh4[nt2][0], bh4[nt2][1]);
                    mma16816(sa[2 * nt2 + 1], ql[k4], bh4[nt2][2], bh4[nt2][3]);
                }
            }
        }

        // ---- scale + causal mask (diag tile only) ----
        const bool diag = (kt == nkv - 1);
#pragma unroll
        for (int nt = 0; nt < 8; nt++) {
            int kg = kt * 64 + nt * 8 + c2;
            sa[nt][0] = (diag && kg     > qg0) ? -1e30f : sa[nt][0] * scale;
            sa[nt][1] = (diag && kg + 1 > qg0) ? -1e30f : sa[nt][1] * scale;
            sa[nt][2] = (diag && kg     > qg1) ? -1e30f : sa[nt][2] * scale;
            sa[nt][3] = (diag && kg + 1 > qg1) ? -1e30f : sa[nt][3] * scale;
        }

        // ---- online softmax ----
        float mx0 = -1e30f, mx1 = -1e30f;
#pragma unroll
        for (int nt = 0; nt < 8; nt++) {
            mx0 = fmaxf(mx0, fmaxf(sa[nt][0], sa[nt][1]));
            mx1 = fmaxf(mx1, fmaxf(sa[nt][2], sa[nt][3]));
        }
        mx0 = fmaxf(mx0, __shfl_xor_sync(0xffffffffu, mx0, 1));
        mx0 = fmaxf(mx0, __shfl_xor_sync(0xffffffffu, mx0, 2));
        mx1 = fmaxf(mx1, __shfl_xor_sync(0xffffffffu, mx1, 1));
        mx1 = fmaxf(mx1, __shfl_xor_sync(0xffffffffu, mx1, 2));
        float mn0 = fmaxf(mrow0, mx0), mn1 = fmaxf(mrow1, mx1);
        float al0 = __expf(mrow0 - mn0), al1 = __expf(mrow1 - mn1);
        mrow0 = mn0; mrow1 = mn1;
        float sum0 = 0.0f, sum1 = 0.0f;
#pragma unroll
        for (int nt = 0; nt < 8; nt++) {
            float p0 = __expf(sa[nt][0] - mn0);
            float p1 = __expf(sa[nt][1] - mn0);
            float p2 = __expf(sa[nt][2] - mn1);
            float p3 = __expf(sa[nt][3] - mn1);
            sa[nt][0] = p0; sa[nt][1] = p1; sa[nt][2] = p2; sa[nt][3] = p3;
            sum0 += p0 + p1; sum1 += p2 + p3;
        }
        sum0 += __shfl_xor_sync(0xffffffffu, sum0, 1);
        sum0 += __shfl_xor_sync(0xffffffffu, sum0, 2);
        sum1 += __shfl_xor_sync(0xffffffffu, sum1, 1);
        sum1 += __shfl_xor_sync(0xffffffffu, sum1, 2);
        lrow0 = lrow0 * al0 + sum0;
        lrow1 = lrow1 * al1 + sum1;
#pragma unroll
        for (int nt = 0; nt < 8; nt++) {
            ctx[nt][0] *= al0; ctx[nt][1] *= al0;
            ctx[nt][2] *= al1; ctx[nt][3] *= al1;
        }

        // ---- ctx += P V (3-term, term-major over all 4 dt) ----
        {
            const int vrow = (lane & 7) + (((lane >> 3) & 1) << 3);
            const int vcol = (lane >> 4) << 3;
#pragma unroll
            for (int kt2 = 0; kt2 < 4; kt2++) {
                uint32_t pa[4], pb[4];
                split2(sa[2 * kt2][0],     sa[2 * kt2][1],     pa[0], pb[0]);
                split2(sa[2 * kt2][2],     sa[2 * kt2][3],     pa[1], pb[1]);
                split2(sa[2 * kt2 + 1][0], sa[2 * kt2 + 1][1], pa[2], pb[2]);
                split2(sa[2 * kt2 + 1][2], sa[2 * kt2 + 1][3], pa[3], pb[3]);
                uint32_t vh4[4][4], vl4[4][4];
#pragma unroll
                for (int dt = 0; dt < 4; dt++) {
                    uint32_t vd = st + 2 * FKTILE_B +
                        (uint32_t)((16 * kt2 + vrow) * FS + dt * 16 + vcol) * 2;
                    ldm_x4_t(vh4[dt], vd);
                    ldm_x4_t(vl4[dt], vd + FKTILE_B);
                }
#pragma unroll
                for (int dt = 0; dt < 4; dt++) {
                    mma16816(ctx[2 * dt],     pa, vh4[dt][0], vh4[dt][1]);
                    mma16816(ctx[2 * dt + 1], pa, vh4[dt][2], vh4[dt][3]);
                }
#pragma unroll
                for (int dt = 0; dt < 4; dt++) {
                    mma16816(ctx[2 * dt],     pa, vl4[dt][0], vl4[dt][1]);
                    mma16816(ctx[2 * dt + 1], pa, vl4[dt][2], vl4[dt][3]);
                }
#pragma unroll
                for (int dt = 0; dt < 4; dt++) {
                    mma16816(ctx[2 * dt],     pb, vh4[dt][0], vh4[dt][1]);
                    mma16816(ctx[2 * dt + 1], pb, vh4[dt][2], vh4[dt][3]);
                }
            }
        }
        __syncthreads();
    }

    // ---- epilogue: normalize, emit ctx hi/lo split [b*T+t][h*HD+hd] ----
    const float il0 = 1.0f / lrow0, il1 = 1.0f / lrow1;
    const int b = bh / H_, h = bh % H_;
    const int t0 = q0 + 16 * w + gr, t1 = t0 + 8;
#pragma unroll
    for (int nt = 0; nt < 8; nt++) {
        int d = nt * 8 + c2;
        size_t i0 = ((size_t)(b * T_ + t0)) * D_ + h * HD_ + d;
        size_t i1 = ((size_t)(b * T_ + t1)) * D_ + h * HD_ + d;
        uint32_t hi0, lo0, hi1, lo1;
        split2(ctx[nt][0] * il0, ctx[nt][1] * il0, hi0, lo0);
        split2(ctx[nt][2] * il1, ctx[nt][3] * il1, hi1, lo1);
        *reinterpret_cast<uint32_t*>(&chi[i0]) = hi0;
        *reinterpret_cast<uint32_t*>(&clo[i0]) = lo0;
        *reinterpret_cast<uint32_t*>(&chi[i1]) = hi1;
        *reinterpret_cast<uint32_t*>(&clo[i1]) = lo1;
    }
}

// ---------------------------------------------------------------------------
// Launch
// ---------------------------------------------------------------------------
extern "C" void kernel_launch(void* const* d_in, const int* in_sizes, int n_in,
                              void* d_out, int out_size)
{
    const float* x  = (const float*)d_in[0];
    const float* Wq = (const float*)d_in[1];
    const float* bq = (const float*)d_in[2];
    const float* Wk = (const float*)d_in[3];
    const float* bk = (const float*)d_in[4];
    const float* Wv = (const float*)d_in[5];
    const float* bv = (const float*)d_in[6];
    const float* Wo = (const float*)d_in[7];
    const float* bo = (const float*)d_in[8];
    float* out = (float*)d_out;

    __nv_bfloat16 *qhi, *qlo, *khi, *klo, *vhi, *vlo, *xhi, *xlo, *whi, *wlo;
    cudaGetSymbolAddress((void**)&qhi, g_qhi);
    cudaGetSymbolAddress((void**)&qlo, g_qlo);
    cudaGetSymbolAddress((void**)&khi, g_khi);
    cudaGetSymbolAddress((void**)&klo, g_klo);
    cudaGetSymbolAddress((void**)&vhi, g_vhi);
    cudaGetSymbolAddress((void**)&vlo, g_vlo);
    cudaGetSymbolAddress((void**)&xhi, g_xhi);
    cudaGetSymbolAddress((void**)&xlo, g_xlo);
    cudaGetSymbolAddress((void**)&whi, g_whi);
    cudaGetSymbolAddress((void**)&wlo, g_wlo);

    cudaFuncSetAttribute(gemm_mma<1>,
                         cudaFuncAttributeMaxDynamicSharedMemorySize, GSMEM);
    cudaFuncSetAttribute(gemm_mma<0>,
                         cudaFuncAttributeMaxDynamicSharedMemorySize, GSMEM);
    cudaFuncSetAttribute(flash_mma,
                         cudaFuncAttributeMaxDynamicSharedMemorySize, FSMEM);

    const int n4x = (int)(MD_ / 4);
    const int n4w = (D_ * D_) / 4;
    dim3 gthr(256);
    dim3 ggrid(D_ / 128, M_ / 128);   // (16, 32)
    dim3 fgrid(T_ / 64, B_ * H_);     // (32, 64)

    // X -> hi/lo split
    conv_split<<<(n4x + 255) / 256, 256>>>(
        (const float4*)x, (uint2*)xhi, (uint2*)xlo, n4x);

    // Q/K/V projections (bf16 hi/lo head-split outputs)
    conv_split<<<(n4w + 255) / 256, 256>>>(
        (const float4*)Wq, (uint2*)whi, (uint2*)wlo, n4w);
    gemm_mma<1><<<ggrid, gthr, GSMEM>>>(xhi, xlo, whi, wlo, bq, nullptr, qhi, qlo);

    conv_split<<<(n4w + 255) / 256, 256>>>(
        (const float4*)Wk, (uint2*)whi, (uint2*)wlo, n4w);
    gemm_mma<1><<<ggrid, gthr, GSMEM>>>(xhi, xlo, whi, wlo, bk, nullptr, khi, klo);

    conv_split<<<(n4w + 255) / 256, 256>>>(
        (const float4*)Wv, (uint2*)whi, (uint2*)wlo, n4w);
    gemm_mma<1><<<ggrid, gthr, GSMEM>>>(xhi, xlo, whi, wlo, bv, nullptr, vhi, vlo);

    // Flash attention on tensor cores; ctx hi/lo into X's buffers
    flash_mma<<<fgrid, 128, FSMEM>>>(qhi, qlo, khi, klo, vhi, vlo, xhi, xlo);

    // O projection (fp32 output)
    conv_split<<<(n4w + 255) / 256, 256>>>(
        (const float4*)Wo, (uint2*)whi, (uint2*)wlo, n4w);
    gemm_mma<0><<<ggrid, gthr, GSMEM>>>(xhi, xlo, whi, wlo, bo, out, nullptr, nullptr);

    (void)in_sizes; (void)n_in; (void)out_size;
}

// round 14
// speedup vs baseline: 1.2413x; 1.2413x over previous
#include <cuda_runtime.h>
#include <cuda_fp16.h>
#include <cuda_bf16.h>
#include <stdint.h>
#include <math.h>

#define B_  2
#define T_  2048
#define D_  2048
#define H_  32
#define HD_ 64
#define M_  (B_ * T_)          // 4096 rows for all GEMMs
#define MD_ ((size_t)M_ * D_)

// ---------------------------------------------------------------------------
// Scratch (device globals — no allocation allowed). 144 MB total — the exact
// footprint of the passing R10 kernel.
//   g_xa/g_xb: fp16 X hi/lo for QKV GEMMs; later REUSED (bitwise) as bf16
//              ctx hi/lo written by flash and read by the O-projection.
//   g_wa:      fp16 W (QKV, one at a time); later REUSED as bf16 Wo-hi.
//   g_wb:      bf16 Wo-lo.
// ---------------------------------------------------------------------------
__device__ __nv_bfloat16 g_qhi[MD_];
__device__ __nv_bfloat16 g_qlo[MD_];
__device__ __nv_bfloat16 g_khi[MD_];
__device__ __nv_bfloat16 g_klo[MD_];
__device__ __nv_bfloat16 g_vhi[MD_];
__device__ __nv_bfloat16 g_vlo[MD_];
__device__ unsigned short g_xa[MD_];               // fp16 Xhi -> bf16 ctx hi
__device__ unsigned short g_xb[MD_];               // fp16 Xlo -> bf16 ctx lo
__device__ unsigned short g_wa[(size_t)D_ * D_];   // fp16 W   -> bf16 Wo hi
__device__ __nv_bfloat16  g_wb[(size_t)D_ * D_];   // bf16 Wo lo

// ---------------------------------------------------------------------------
// PTX helpers (plain sm_80-era; nothing 'a'-gated)
// ---------------------------------------------------------------------------
__device__ __forceinline__ uint32_t smem_u32(const void* p) {
    uint32_t a;
    asm("{ .reg .u64 t; cvta.to.shared.u64 t, %1; cvt.u32.u64 %0, t; }"
        : "=r"(a) : "l"(p));
    return a;
}
#define CP_ASYNC16(dst, src) \
    asm volatile("cp.async.cg.shared.global [%0], [%1], 16;" \
                 :: "r"(dst), "l"(src))
#define CP_COMMIT  asm volatile("cp.async.commit_group;" ::: "memory")
#define CP_WAIT(n) asm volatile("cp.async.wait_group %0;" :: "n"(n) : "memory")

__device__ __forceinline__ void ldm_x4(uint32_t (&r)[4], uint32_t addr) {
    asm volatile("ldmatrix.sync.aligned.m8n8.x4.shared.b16 {%0,%1,%2,%3}, [%4];"
                 : "=r"(r[0]), "=r"(r[1]), "=r"(r[2]), "=r"(r[3]) : "r"(addr));
}
__device__ __forceinline__ void ldm_x4_t(uint32_t (&r)[4], uint32_t addr) {
    asm volatile("ldmatrix.sync.aligned.m8n8.x4.trans.shared.b16 {%0,%1,%2,%3}, [%4];"
                 : "=r"(r[0]), "=r"(r[1]), "=r"(r[2]), "=r"(r[3]) : "r"(addr));
}
// bf16 x bf16 -> fp32 accum (passing R10 path)
__device__ __forceinline__ void mma_bf16(float (&d)[4], const uint32_t (&a)[4],
                                         uint32_t b0, uint32_t b1) {
    asm volatile(
        "mma.sync.aligned.m16n8k16.row.col.f32.bf16.bf16.f32 "
        "{%0,%1,%2,%3},{%4,%5,%6,%7},{%8,%9},{%0,%1,%2,%3};"
        : "+f"(d[0]), "+f"(d[1]), "+f"(d[2]), "+f"(d[3])
        : "r"(a[0]), "r"(a[1]), "r"(a[2]), "r"(a[3]), "r"(b0), "r"(b1));
}
// fp16 x fp16 -> fp32 accum (the one new instruction under test)
__device__ __forceinline__ void mma_f16(float (&d)[4], const uint32_t (&a)[4],
                                        uint32_t b0, uint32_t b1) {
    asm volatile(
        "mma.sync.aligned.m16n8k16.row.col.f32.f16.f16.f32 "
        "{%0,%1,%2,%3},{%4,%5,%6,%7},{%8,%9},{%0,%1,%2,%3};"
        : "+f"(d[0]), "+f"(d[1]), "+f"(d[2]), "+f"(d[3])
        : "r"(a[0]), "r"(a[1]), "r"(a[2]), "r"(a[3]), "r"(b0), "r"(b1));
}
__device__ __forceinline__ uint32_t pack_bf16x2(__nv_bfloat16 lo, __nv_bfloat16 hi) {
    __nv_bfloat162 v(lo, hi);
    return *reinterpret_cast<uint32_t*>(&v);
}
// fp32 pair -> packed bf16 hi pair + bf16 residual pair (R10 helper)
__device__ __forceinline__ void split2b(float a, float b, uint32_t& hi, uint32_t& lo) {
    __nv_bfloat16 ha = __float2bfloat16_rn(a);
    __nv_bfloat16 hb = __float2bfloat16_rn(b);
    hi = pack_bf16x2(ha, hb);
    lo = pack_bf16x2(__float2bfloat16_rn(a - __bfloat162float(ha)),
                     __float2bfloat16_rn(b - __bfloat162float(hb)));
}
__device__ __forceinline__ uint32_t h2bits(__half2 v) {
    return *reinterpret_cast<uint32_t*>(&v);
}
// fp32 pair -> packed fp16 hi pair + fp16 residual pair
__device__ __forceinline__ void split2h(float a, float b, uint32_t& hi, uint32_t& lo) {
    __half ha = __float2half_rn(a);
    __half hb = __float2half_rn(b);
    hi = h2bits(__half2(ha, hb));
    lo = h2bits(__half2(__float2half_rn(a - __half2float(ha)),
                        __float2half_rn(b - __half2float(hb))));
}

// ---------------------------------------------------------------------------
// Converters
// ---------------------------------------------------------------------------
__global__ __launch_bounds__(256) void conv_split_h(   // fp32 -> fp16 hi/lo
    const float4* __restrict__ src,
    uint2* __restrict__ hi, uint2* __restrict__ lo, int n4)
{
    int i = blockIdx.x * 256 + threadIdx.x;
    if (i >= n4) return;
    float4 f = src[i];
    uint2 h, l;
    split2h(f.x, f.y, h.x, l.x);
    split2h(f.z, f.w, h.y, l.y);
    hi[i] = h;
    lo[i] = l;
}
__global__ __launch_bounds__(256) void conv_split_b(   // fp32 -> bf16 hi/lo
    const float4* __restrict__ src,
    uint2* __restrict__ hi, uint2* __restrict__ lo, int n4)
{
    int i = blockIdx.x * 256 + threadIdx.x;
    if (i >= n4) return;
    float4 f = src[i];
    uint2 h, l;
    split2b(f.x, f.y, h.x, l.x);
    split2b(f.z, f.w, h.y, l.y);
    hi[i] = h;
    lo[i] = l;
}
__global__ __launch_bounds__(256) void conv_half(      // fp32 -> fp16 single
    const float4* __restrict__ src, uint2* __restrict__ dst, int n4)
{
    int i = blockIdx.x * 256 + threadIdx.x;
    if (i >= n4) return;
    float4 f = src[i];
    uint2 o;
    o.x = h2bits(__floats2half2_rn(f.x, f.y));
    o.y = h2bits(__floats2half2_rn(f.z, f.w));
    dst[i] = o;
}

// ---------------------------------------------------------------------------
// NEW: QKV GEMM, fp16 asymmetric 2-term split:
//   C = (Ahi + Alo)_fp16 @ fp16(W)^T + bias;  out: head-split bf16 hi/lo.
// CTA 128x128, BK=32, 256 thr. Stage = 3 tiles (Ahi, Alo, W), double-buffered.
// ---------------------------------------------------------------------------
#define TILE_B    10240          // bytes per 128x32 tile (stride-40 rows)
#define STAGE3_B  (3 * TILE_B)   // 30720
#define G3SMEM    (2 * STAGE3_B) // 61440 B

__global__ __launch_bounds__(256, 2) void gemm_f16(
    const unsigned short* __restrict__ Ahi,
    const unsigned short* __restrict__ Alo,
    const unsigned short* __restrict__ W,
    const float* __restrict__ bias,
    __nv_bfloat16* __restrict__ outh,
    __nv_bfloat16* __restrict__ outl)
{
    extern __shared__ char smraw[];
    const uint32_t sbase = smem_u32(smraw);

    const int tid  = threadIdx.x;
    const int lane = tid & 31;
    const int wid  = tid >> 5;
    const int wm   = wid & 3;
    const int wn   = wid >> 2;
    const int m0   = blockIdx.y * 128;
    const int n0   = blockIdx.x * 128;

    float acc[2][8][4];
#pragma unroll
    for (int mt = 0; mt < 2; mt++)
#pragma unroll
        for (int nt = 0; nt < 8; nt++)
#pragma unroll
            for (int e = 0; e < 4; e++) acc[mt][nt][e] = 0.0f;

    auto load_stage = [&](int s, int k0) {
        const uint32_t st = sbase + (uint32_t)s * STAGE3_B;
#pragma unroll
        for (int t8 = 0; t8 < 6; t8++) {
            int c    = tid + t8 * 256;        // 0..1535
            int tile = c >> 9;                // 0..2
            int rem  = c & 511;
            int r    = rem >> 2;
            int kc   = (rem & 3) * 8;
            uint32_t dst = st + (uint32_t)tile * TILE_B + (uint32_t)(r * 40 + kc) * 2;
            const unsigned short* g;
            if (tile == 0)      g = Ahi + (size_t)(m0 + r) * 2048 + k0 + kc;
            else if (tile == 1) g = Alo + (size_t)(m0 + r) * 2048 + k0 + kc;
            else                g = W   + (size_t)(n0 + r) * 2048 + k0 + kc;
            CP_ASYNC16(dst, g);
        }
    };

    load_stage(0, 0);
    CP_COMMIT;

    const int NIT = 2048 / 32;
    for (int it = 0; it < NIT; it++) {
        const int s = it & 1;
        if (it + 1 < NIT) {
            load_stage(s ^ 1, (it + 1) * 32);
            CP_COMMIT;
            CP_WAIT(1);
        } else {
            CP_WAIT(0);
        }
        __syncthreads();

        const uint32_t st = sbase + (uint32_t)s * STAGE3_B;
#pragma unroll
        for (int ks = 0; ks < 2; ks++) {
            uint32_t aHi[2][4], aLo[2][4];
            const int arow = lane & 15;
            const int akof = ks * 16 + ((lane >> 4) << 3);
#pragma unroll
            for (int mt = 0; mt < 2; mt++) {
                uint32_t ad = st + (uint32_t)((wm * 32 + mt * 16 + arow) * 40 + akof) * 2;
                ldm_x4(aHi[mt], ad);
                ldm_x4(aLo[mt], ad + TILE_B);
            }
            const int brow = (lane & 7) + ((lane >> 4) << 3);
            const int bkof = ks * 16 + (((lane >> 3) & 1) << 3);
#pragma unroll
            for (int pr = 0; pr < 2; pr++) {
                uint32_t bW[2][4];
#pragma unroll
                for (int q = 0; q < 2; q++) {
                    int nt2 = pr * 2 + q;
                    uint32_t bd = st + 2 * TILE_B +
                        (uint32_t)((wn * 64 + nt2 * 16 + brow) * 40 + bkof) * 2;
                    ldm_x4(bW[q], bd);
                }
#pragma unroll
                for (int q = 0; q < 2; q++) {   // term 1: aHi * W
                    int nt2 = pr * 2 + q;
                    mma_f16(acc[0][2 * nt2],     aHi[0], bW[q][0], bW[q][1]);
                    mma_f16(acc[0][2 * nt2 + 1], aHi[0], bW[q][2], bW[q][3]);
                    mma_f16(acc[1][2 * nt2],     aHi[1], bW[q][0], bW[q][1]);
                    mma_f16(acc[1][2 * nt2 + 1], aHi[1], bW[q][2], bW[q][3]);
                }
#pragma unroll
                for (int q = 0; q < 2; q++) {   // term 2: aLo * W
                    int nt2 = pr * 2 + q;
                    mma_f16(acc[0][2 * nt2],     aLo[0], bW[q][0], bW[q][1]);
                    mma_f16(acc[0][2 * nt2 + 1], aLo[0], bW[q][2], bW[q][3]);
                    mma_f16(acc[1][2 * nt2],     aLo[1], bW[q][0], bW[q][1]);
                    mma_f16(acc[1][2 * nt2 + 1], aLo[1], bW[q][2], bW[q][3]);
                }
            }
        }
        __syncthreads();
    }

    // ---- epilogue: bias, head-split, bf16 hi/lo out ----
    const int gr = lane >> 2;
    const int c2 = (lane & 3) * 2;
#pragma unroll
    for (int mt = 0; mt < 2; mt++) {
#pragma unroll
        for (int nt = 0; nt < 8; nt++) {
            int m = m0 + wm * 32 + mt * 16 + gr;
            int n = n0 + wn * 64 + nt * 8 + c2;
            float b0 = bias[n], b1 = bias[n + 1];
            float f00 = acc[mt][nt][0] + b0, f01 = acc[mt][nt][1] + b1;
            float f10 = acc[mt][nt][2] + b0, f11 = acc[mt][nt][3] + b1;
            int b  = m >> 11, t = m & (T_ - 1);
            int h  = n >> 6,  hd = n & (HD_ - 1);
            size_t i0 = (((size_t)(b * H_ + h)) * T_ + t) * HD_ + hd;
            size_t i1 = (((size_t)(b * H_ + h)) * T_ + (t + 8)) * HD_ + hd;
            uint32_t hi0, lo0, hi1, lo1;
            split2b(f00, f01, hi0, lo0);
            split2b(f10, f11, hi1, lo1);
            *reinterpret_cast<uint32_t*>(&outh[i0]) = hi0;
            *reinterpret_cast<uint32_t*>(&outl[i0]) = lo0;
            *reinterpret_cast<uint32_t*>(&outh[i1]) = hi1;
            *reinterpret_cast<uint32_t*>(&outl[i1]) = lo1;
        }
    }
}

// ---------------------------------------------------------------------------
// O-projection GEMM: bf16 3-term split, fp32 out — structure of the passing
// R10 kernel (MODE 0 path). Stage = 4 tiles (Ahi, Alo, Whi, Wlo).
// ---------------------------------------------------------------------------
#define STAGE4_B  (4 * TILE_B)   // 40960
#define G4SMEM    (2 * STAGE4_B) // 81920 B

__global__ __launch_bounds__(256, 2) void gemm_bf16(
    const __nv_bfloat16* __restrict__ Ahi,
    const __nv_bfloat16* __restrict__ Alo,
    const __nv_bfloat16* __restrict__ Whi,
    const __nv_bfloat16* __restrict__ Wlo,
    const float* __restrict__ bias,
    float* __restrict__ outf)
{
    extern __shared__ char smraw[];
    const uint32_t sbase = smem_u32(smraw);

    const int tid  = threadIdx.x;
    const int lane = tid & 31;
    const int wid  = tid >> 5;
    const int wm   = wid & 3;
    const int wn   = wid >> 2;
    const int m0   = blockIdx.y * 128;
    const int n0   = blockIdx.x * 128;

    float acc[2][8][4];
#pragma unroll
    for (int mt = 0; mt < 2; mt++)
#pragma unroll
        for (int nt = 0; nt < 8; nt++)
#pragma unroll
            for (int e = 0; e < 4; e++) acc[mt][nt][e] = 0.0f;

    auto load_stage = [&](int s, int k0) {
        const uint32_t st = sbase + (uint32_t)s * STAGE4_B;
#pragma unroll
        for (int t8 = 0; t8 < 8; t8++) {
            int c    = tid + t8 * 256;
            int tile = c >> 9;
            int rem  = c & 511;
            int r    = rem >> 2;
            int kc   = (rem & 3) * 8;
            uint32_t dst = st + (uint32_t)tile * TILE_B + (uint32_t)(r * 40 + kc) * 2;
            const __nv_bfloat16* g;
            if (tile == 0)      g = Ahi + (size_t)(m0 + r) * 2048 + k0 + kc;
            else if (tile == 1) g = Alo + (size_t)(m0 + r) * 2048 + k0 + kc;
            else if (tile == 2) g = Whi + (size_t)(n0 + r) * 2048 + k0 + kc;
            else                g = Wlo + (size_t)(n0 + r) * 2048 + k0 + kc;
            CP_ASYNC16(dst, g);
        }
    };

    load_stage(0, 0);
    CP_COMMIT;

    const int NIT = 2048 / 32;
    for (int it = 0; it < NIT; it++) {
        const int s = it & 1;
        if (it + 1 < NIT) {
            load_stage(s ^ 1, (it + 1) * 32);
            CP_COMMIT;
            CP_WAIT(1);
        } else {
            CP_WAIT(0);
        }
        __syncthreads();

        const uint32_t st = sbase + (uint32_t)s * STAGE4_B;
#pragma unroll
        for (int ks = 0; ks < 2; ks++) {
            uint32_t aHi[2][4], aLo[2][4];
            const int arow = lane & 15;
            const int akof = ks * 16 + ((lane >> 4) << 3);
#pragma unroll
            for (int mt = 0; mt < 2; mt++) {
                uint32_t ad = st + (uint32_t)((wm * 32 + mt * 16 + arow) * 40 + akof) * 2;
                ldm_x4(aHi[mt], ad);
                ldm_x4(aLo[mt], ad + TILE_B);
            }
            const int brow = (lane & 7) + ((lane >> 4) << 3);
            const int bkof = ks * 16 + (((lane >> 3) & 1) << 3);
#pragma unroll
            for (int pr = 0; pr < 2; pr++) {
                uint32_t bHi[2][4], bLo[2][4];
#pragma unroll
                for (int q = 0; q < 2; q++) {
                    int nt2 = pr * 2 + q;
                    uint32_t bd = st + 2 * TILE_B +
                        (uint32_t)((wn * 64 + nt2 * 16 + brow) * 40 + bkof) * 2;
                    ldm_x4(bHi[q], bd);
                    ldm_x4(bLo[q], bd + TILE_B);
                }
#pragma unroll
                for (int q = 0; q < 2; q++) {
                    int nt2 = pr * 2 + q;
                    mma_bf16(acc[0][2 * nt2],     aHi[0], bHi[q][0], bHi[q][1]);
                    mma_bf16(acc[0][2 * nt2 + 1], aHi[0], bHi[q][2], bHi[q][3]);
                    mma_bf16(acc[1][2 * nt2],     aHi[1], bHi[q][0], bHi[q][1]);
                    mma_bf16(acc[1][2 * nt2 + 1], aHi[1], bHi[q][2], bHi[q][3]);
                }
#pragma unroll
                for (int q = 0; q < 2; q++) {
                    int nt2 = pr * 2 + q;
                    mma_bf16(acc[0][2 * nt2],     aHi[0], bLo[q][0], bLo[q][1]);
                    mma_bf16(acc[0][2 * nt2 + 1], aHi[0], bLo[q][2], bLo[q][3]);
                    mma_bf16(acc[1][2 * nt2],     aHi[1], bLo[q][0], bLo[q][1]);
                    mma_bf16(acc[1][2 * nt2 + 1], aHi[1], bLo[q][2], bLo[q][3]);
                }
#pragma unroll
                for (int q = 0; q < 2; q++) {
                    int nt2 = pr * 2 + q;
                    mma_bf16(acc[0][2 * nt2],     aLo[0], bHi[q][0], bHi[q][1]);
                    mma_bf16(acc[0][2 * nt2 + 1], aLo[0], bHi[q][2], bHi[q][3]);
                    mma_bf16(acc[1][2 * nt2],     aLo[1], bHi[q][0], bHi[q][1]);
                    mma_bf16(acc[1][2 * nt2 + 1], aLo[1], bHi[q][2], bHi[q][3]);
                }
            }
        }
        __syncthreads();
    }

    const int gr = lane >> 2;
    const int c2 = (lane & 3) * 2;
#pragma unroll
    for (int mt = 0; mt < 2; mt++) {
#pragma unroll
        for (int nt = 0; nt < 8; nt++) {
            int m = m0 + wm * 32 + mt * 16 + gr;
            int n = n0 + wn * 64 + nt * 8 + c2;
            float b0 = bias[n], b1 = bias[n + 1];
            *reinterpret_cast<float2*>(&outf[(size_t)m * D_ + n])
                = make_float2(acc[mt][nt][0] + b0, acc[mt][nt][1] + b1);
            *reinterpret_cast<float2*>(&outf[(size_t)(m + 8) * D_ + n])
                = make_float2(acc[mt][nt][2] + b0, acc[mt][nt][3] + b1);
        }
    }
}

// ---------------------------------------------------------------------------
// Flash attention (causal) — byte-identical logic to the PASSING R10 kernel.
// bf16, 3-term QK^T, 3-term PV, term-major. Grid (32, 64), 128 thr.
// ---------------------------------------------------------------------------
#define FS        72
#define FKTILE_B  (64 * FS * 2)
#define FQ_B      (2 * FKTILE_B)
#define FSTG_B    (4 * FKTILE_B)
#define FSMEM     (FQ_B + 2 * FSTG_B)     // 92160 B

__global__ __launch_bounds__(128, 2) void flash_mma(
    const __nv_bfloat16* __restrict__ qhi_g, const __nv_bfloat16* __restrict__ qlo_g,
    const __nv_bfloat16* __restrict__ khi_g, const __nv_bfloat16* __restrict__ klo_g,
    const __nv_bfloat16* __restrict__ vhi_g, const __nv_bfloat16* __restrict__ vlo_g,
    __nv_bfloat16* __restrict__ chi, __nv_bfloat16* __restrict__ clo)
{
    extern __shared__ char fsm[];
    const uint32_t sb = smem_u32(fsm);
    const int tid  = threadIdx.x;
    const int lane = tid & 31;
    const int w    = tid >> 5;
    const int bh   = blockIdx.y;
    const int q0   = (gridDim.x - 1 - blockIdx.x) * 64;
    const size_t hb = (size_t)bh * T_ * HD_;

#pragma unroll
    for (int m = 0; m < 2; m++) {
        const __nv_bfloat16* src = m ? qlo_g : qhi_g;
        uint32_t dstb = sb + (uint32_t)m * FKTILE_B;
#pragma unroll
        for (int i = 0; i < 4; i++) {
            int c = tid + i * 128;
            int r = c >> 3, ch = (c & 7) * 8;
            CP_ASYNC16(dstb + (uint32_t)(r * FS + ch) * 2,
                       src + hb + (size_t)(q0 + r) * HD_ + ch);
        }
    }
    CP_COMMIT;

    auto load_kv = [&](int s, int k0) {
        uint32_t st = sb + FQ_B + (uint32_t)s * FSTG_B;
        const __nv_bfloat16* srcs[4] = {khi_g, klo_g, vhi_g, vlo_g};
#pragma unroll
        for (int m = 0; m < 4; m++) {
#pragma unroll
            for (int i = 0; i < 4; i++) {
                int c = tid + i * 128;
                int r = c >> 3, ch = (c & 7) * 8;
                CP_ASYNC16(st + (uint32_t)m * FKTILE_B + (uint32_t)(r * FS + ch) * 2,
                           srcs[m] + hb + (size_t)(k0 + r) * HD_ + ch);
            }
        }
    };
    load_kv(0, 0);
    CP_COMMIT;
    CP_WAIT(1);
    __syncthreads();

    uint32_t qh[4][4], ql[4][4];
    {
        int arow = lane & 15, akof = (lane >> 4) * 8;
#pragma unroll
        for (int kt = 0; kt < 4; kt++) {
            uint32_t ad = sb + (uint32_t)((16 * w + arow) * FS + kt * 16 + akof) * 2;
            ldm_x4(qh[kt], ad);
            ldm_x4(ql[kt], ad + FKTILE_B);
        }
    }

    float ctx[8][4];
#pragma unroll
    for (int nt = 0; nt < 8; nt++)
#pragma unroll
        for (int e = 0; e < 4; e++) ctx[nt][e] = 0.0f;
    float mrow0 = -1e30f, mrow1 = -1e30f, lrow0 = 0.0f, lrow1 = 0.0f;

    const int nkv = (q0 >> 6) + 1;
    const int gr  = lane >> 2;
    const int c2  = (lane & 3) * 2;
    const float scale = 0.125f;
    const int qg0 = q0 + 16 * w + gr;
    const int qg1 = qg0 + 8;

    for (int kt = 0; kt < nkv; kt++) {
        const int s = kt & 1;
        if (kt + 1 < nkv) {
            load_kv(s ^ 1, (kt + 1) * 64);
            CP_COMMIT;
            CP_WAIT(1);
        } else {
            CP_WAIT(0);
        }
        __syncthreads();
        const uint32_t st = sb + FQ_B + (uint32_t)s * FSTG_B;

        float sa[8][4];
#pragma unroll
        for (int nt = 0; nt < 8; nt++)
#pragma unroll
            for (int e = 0; e < 4; e++) sa[nt][e] = 0.0f;
        {
            const int brow = (lane & 7) + ((lane >> 4) << 3);
            const int bkof = ((lane >> 3) & 1) << 3;
#pragma unroll
            for (int k4 = 0; k4 < 4; k4++) {
                uint32_t bh4[4][4], bl4[4][4];
#pragma unroll
                for (int nt2 = 0; nt2 < 4; nt2++) {
                    uint32_t bd = st +
                        (uint32_t)((nt2 * 16 + brow) * FS + k4 * 16 + bkof) * 2;
                    ldm_x4(bh4[nt2], bd);
                    ldm_x4(bl4[nt2], bd + FKTILE_B);
                }
#pragma unroll
                for (int nt2 = 0; nt2 < 4; nt2++) {
                    mma_bf16(sa[2 * nt2],     qh[k4], bh4[nt2][0], bh4[nt2][1]);
                    mma_bf16(sa[2 * nt2 + 1], qh[k4], bh4[nt2][2], bh4[nt2][3]);
                }
#pragma unroll
                for (int nt2 = 0; nt2 < 4; nt2++) {
                    mma_bf16(sa[2 * nt2],     qh[k4], bl4[nt2][0], bl4[nt2][1]);
                    mma_bf16(sa[2 * nt2 + 1], qh[k4], bl4[nt2][2], bl4[nt2][3]);
                }
#pragma unroll
                for (int nt2 = 0; nt2 < 4; nt2++) {
                    mma_bf16(sa[2 * nt2],     ql[k4], bh4[nt2][0], bh4[nt2][1]);
                    mma_bf16(sa[2 * nt2 + 1], ql[k4], bh4[nt2][2], bh4[nt2][3]);
                }
            }
        }

        const bool diag = (kt == nkv - 1);
#pragma unroll
        for (int nt = 0; nt < 8; nt++) {
            int kg = kt * 64 + nt * 8 + c2;
            sa[nt][0] = (diag && kg     > qg0) ? -1e30f : sa[nt][0] * scale;
            sa[nt][1] = (diag && kg + 1 > qg0) ? -1e30f : sa[nt][1] * scale;
            sa[nt][2] = (diag && kg     > qg1) ? -1e30f : sa[nt][2] * scale;
            sa[nt][3] = (diag && kg + 1 > qg1) ? -1e30f : sa[nt][3] * scale;
        }

        float mx0 = -1e30f, mx1 = -1e30f;
#pragma unroll
        for (int nt = 0; nt < 8; nt++) {
            mx0 = fmaxf(mx0, fmaxf(sa[nt][0], sa[nt][1]));
            mx1 = fmaxf(mx1, fmaxf(sa[nt][2], sa[nt][3]));
        }
        mx0 = fmaxf(mx0, __shfl_xor_sync(0xffffffffu, mx0, 1));
        mx0 = fmaxf(mx0, __shfl_xor_sync(0xffffffffu, mx0, 2));
        mx1 = fmaxf(mx1, __shfl_xor_sync(0xffffffffu, mx1, 1));
        mx1 = fmaxf(mx1, __shfl_xor_sync(0xffffffffu, mx1, 2));
        float mn0 = fmaxf(mrow0, mx0), mn1 = fmaxf(mrow1, mx1);
        float al0 = __expf(mrow0 - mn0), al1 = __expf(mrow1 - mn1);
        mrow0 = mn0; mrow1 = mn1;
        float sum0 = 0.0f, sum1 = 0.0f;
#pragma unroll
        for (int nt = 0; nt < 8; nt++) {
            float p0 = __expf(sa[nt][0] - mn0);
            float p1 = __expf(sa[nt][1] - mn0);
            float p2 = __expf(sa[nt][2] - mn1);
            float p3 = __expf(sa[nt][3] - mn1);
            sa[nt][0] = p0; sa[nt][1] = p1; sa[nt][2] = p2; sa[nt][3] = p3;
            sum0 += p0 + p1; sum1 += p2 + p3;
        }
        sum0 += __shfl_xor_sync(0xffffffffu, sum0, 1);
        sum0 += __shfl_xor_sync(0xffffffffu, sum0, 2);
        sum1 += __shfl_xor_sync(0xffffffffu, sum1, 1);
        sum1 += __shfl_xor_sync(0xffffffffu, sum1, 2);
        lrow0 = lrow0 * al0 + sum0;
        lrow1 = lrow1 * al1 + sum1;
#pragma unroll
        for (int nt = 0; nt < 8; nt++) {
            ctx[nt][0] *= al0; ctx[nt][1] *= al0;
            ctx[nt][2] *= al1; ctx[nt][3] *= al1;
        }

        {
            const int vrow = (lane & 7) + (((lane >> 3) & 1) << 3);
            const int vcol = (lane >> 4) << 3;
#pragma unroll
            for (int kt2 = 0; kt2 < 4; kt2++) {
                uint32_t pa[4], pb[4];
                split2b(sa[2 * kt2][0],     sa[2 * kt2][1],     pa[0], pb[0]);
                split2b(sa[2 * kt2][2],     sa[2 * kt2][3],     pa[1], pb[1]);
                split2b(sa[2 * kt2 + 1][0], sa[2 * kt2 + 1][1], pa[2], pb[2]);
                split2b(sa[2 * kt2 + 1][2], sa[2 * kt2 + 1][3], pa[3], pb[3]);
                uint32_t vh4[4][4], vl4[4][4];
#pragma unroll
                for (int dt = 0; dt < 4; dt++) {
                    uint32_t vd = st + 2 * FKTILE_B +
                        (uint32_t)((16 * kt2 + vrow) * FS + dt * 16 + vcol) * 2;
                    ldm_x4_t(vh4[dt], vd);
                    ldm_x4_t(vl4[dt], vd + FKTILE_B);
                }
#pragma unroll
                for (int dt = 0; dt < 4; dt++) {
                    mma_bf16(ctx[2 * dt],     pa, vh4[dt][0], vh4[dt][1]);
                    mma_bf16(ctx[2 * dt + 1], pa, vh4[dt][2], vh4[dt][3]);
                }
#pragma unroll
                for (int dt = 0; dt < 4; dt++) {
                    mma_bf16(ctx[2 * dt],     pa, vl4[dt][0], vl4[dt][1]);
                    mma_bf16(ctx[2 * dt + 1], pa, vl4[dt][2], vl4[dt][3]);
                }
#pragma unroll
                for (int dt = 0; dt < 4; dt++) {
                    mma_bf16(ctx[2 * dt],     pb, vh4[dt][0], vh4[dt][1]);
                    mma_bf16(ctx[2 * dt + 1], pb, vh4[dt][2], vh4[dt][3]);
                }
            }
        }
        __syncthreads();
    }

    const float il0 = 1.0f / lrow0, il1 = 1.0f / lrow1;
    const int b = bh / H_, h = bh % H_;
    const int t0 = q0 + 16 * w + gr, t1 = t0 + 8;
#pragma unroll
    for (int nt = 0; nt < 8; nt++) {
        int d = nt * 8 + c2;
        size_t i0 = ((size_t)(b * T_ + t0)) * D_ + h * HD_ + d;
        size_t i1 = ((size_t)(b * T_ + t1)) * D_ + h * HD_ + d;
        uint32_t hi0, lo0, hi1, lo1;
        split2b(ctx[nt][0] * il0, ctx[nt][1] * il0, hi0, lo0);
        split2b(ctx[nt][2] * il1, ctx[nt][3] * il1, hi1, lo1);
        *reinterpret_cast<uint32_t*>(&chi[i0]) = hi0;
        *reinterpret_cast<uint32_t*>(&clo[i0]) = lo0;
        *reinterpret_cast<uint32_t*>(&chi[i1]) = hi1;
        *reinterpret_cast<uint32_t*>(&clo[i1]) = lo1;
    }
}

// ---------------------------------------------------------------------------
// Launch
// ---------------------------------------------------------------------------
extern "C" void kernel_launch(void* const* d_in, const int* in_sizes, int n_in,
                              void* d_out, int out_size)
{
    const float* x  = (const float*)d_in[0];
    const float* Wq = (const float*)d_in[1];
    const float* bq = (const float*)d_in[2];
    const float* Wk = (const float*)d_in[3];
    const float* bk = (const float*)d_in[4];
    const float* Wv = (const float*)d_in[5];
    const float* bv = (const float*)d_in[6];
    const float* Wo = (const float*)d_in[7];
    const float* bo = (const float*)d_in[8];
    float* out = (float*)d_out;

    __nv_bfloat16 *qhi, *qlo, *khi, *klo, *vhi, *vlo, *wb;
    unsigned short *xa, *xb, *wa;
    cudaGetSymbolAddress((void**)&qhi, g_qhi);
    cudaGetSymbolAddress((void**)&qlo, g_qlo);
    cudaGetSymbolAddress((void**)&khi, g_khi);
    cudaGetSymbolAddress((void**)&klo, g_klo);
    cudaGetSymbolAddress((void**)&vhi, g_vhi);
    cudaGetSymbolAddress((void**)&vlo, g_vlo);
    cudaGetSymbolAddress((void**)&xa,  g_xa);
    cudaGetSymbolAddress((void**)&xb,  g_xb);
    cudaGetSymbolAddress((void**)&wa,  g_wa);
    cudaGetSymbolAddress((void**)&wb,  g_wb);

    cudaFuncSetAttribute(gemm_f16,
                         cudaFuncAttributeMaxDynamicSharedMemorySize, G3SMEM);
    cudaFuncSetAttribute(gemm_bf16,
                         cudaFuncAttributeMaxDynamicSharedMemorySize, G4SMEM);
    cudaFuncSetAttribute(flash_mma,
                         cudaFuncAttributeMaxDynamicSharedMemorySize, FSMEM);

    const int n4x = (int)(MD_ / 4);
    const int n4w = (D_ * D_) / 4;
    dim3 gthr(256);
    dim3 ggrid(D_ / 128, M_ / 128);   // (16, 32)
    dim3 fgrid(T_ / 64, B_ * H_);     // (32, 64)

    // X -> fp16 hi/lo split (into xa/xb)
    conv_split_h<<<(n4x + 255) / 256, 256>>>(
        (const float4*)x, (uint2*)xa, (uint2*)xb, n4x);

    // Q/K/V projections: fp16 2-term GEMM -> bf16 hi/lo head-split
    conv_half<<<(n4w + 255) / 256, 256>>>((const float4*)Wq, (uint2*)wa, n4w);
    gemm_f16<<<ggrid, gthr, G3SMEM>>>(xa, xb, wa, bq, qhi, qlo);

    conv_half<<<(n4w + 255) / 256, 256>>>((const float4*)Wk, (uint2*)wa, n4w);
    gemm_f16<<<ggrid, gthr, G3SMEM>>>(xa, xb, wa, bk, khi, klo);

    conv_half<<<(n4w + 255) / 256, 256>>>((const float4*)Wv, (uint2*)wa, n4w);
    gemm_f16<<<ggrid, gthr, G3SMEM>>>(xa, xb, wa, bv, vhi, vlo);

    // Flash attention (bf16, passing R10 kernel); ctx bf16 hi/lo into xa/xb
    flash_mma<<<fgrid, 128, FSMEM>>>(
        qhi, qlo, khi, klo, vhi, vlo,
        (__nv_bfloat16*)xa, (__nv_bfloat16*)xb);

    // O projection: bf16 3-term GEMM (Wo split into wa-as-bf16 / wb)
    conv_split_b<<<(n4w + 255) / 256, 256>>>(
        (const float4*)Wo, (uint2*)wa, (uint2*)wb, n4w);
    gemm_bf16<<<ggrid, gthr, G4SMEM>>>(
        (const __nv_bfloat16*)xa, (const __nv_bfloat16*)xb,
        (const __nv_bfloat16*)wa, wb, bo, out);

    (void)in_sizes; (void)n_in; (void)out_size;
}

// round 16
// speedup vs baseline: 1.5190x; 1.2237x over previous
#include <cuda_runtime.h>
#include <cuda_fp16.h>
#include <stdint.h>
#include <math.h>

#define B_  2
#define T_  2048
#define D_  2048
#define H_  32
#define HD_ 64
#define M_  (B_ * T_)          // 4096 rows for all GEMMs
#define MD_ ((size_t)M_ * D_)

// ---------------------------------------------------------------------------
// Scratch (device globals — no allocation allowed). ~104 MB total.
// g_xa/g_xb: fp16 X hi/lo for QKV GEMMs; later fp16 ctx hi/lo for O-proj.
// g_wa:      fp16 W, one weight at a time.
// ---------------------------------------------------------------------------
__device__ unsigned short g_qhi[MD_];   // fp16 Q hi, head-split
__device__ unsigned short g_qlo[MD_];   // fp16 Q lo
__device__ unsigned short g_k[MD_];     // fp16 K
__device__ unsigned short g_v[MD_];     // fp16 V
__device__ unsigned short g_xa[MD_];    // fp16 X hi -> ctx hi
__device__ unsigned short g_xb[MD_];    // fp16 X lo -> ctx lo
__device__ unsigned short g_wa[(size_t)D_ * D_];

// ---------------------------------------------------------------------------
// PTX helpers (plain sm_80-era; nothing 'a'-gated)
// ---------------------------------------------------------------------------
__device__ __forceinline__ uint32_t smem_u32(const void* p) {
    uint32_t a;
    asm("{ .reg .u64 t; cvta.to.shared.u64 t, %1; cvt.u32.u64 %0, t; }"
        : "=r"(a) : "l"(p));
    return a;
}
#define CP_ASYNC16(dst, src) \
    asm volatile("cp.async.cg.shared.global [%0], [%1], 16;" \
                 :: "r"(dst), "l"(src))
#define CP_COMMIT  asm volatile("cp.async.commit_group;" ::: "memory")
#define CP_WAIT(n) asm volatile("cp.async.wait_group %0;" :: "n"(n) : "memory")

__device__ __forceinline__ void ldm_x4(uint32_t (&r)[4], uint32_t addr) {
    asm volatile("ldmatrix.sync.aligned.m8n8.x4.shared.b16 {%0,%1,%2,%3}, [%4];"
                 : "=r"(r[0]), "=r"(r[1]), "=r"(r[2]), "=r"(r[3]) : "r"(addr));
}
__device__ __forceinline__ void ldm_x4_t(uint32_t (&r)[4], uint32_t addr) {
    asm volatile("ldmatrix.sync.aligned.m8n8.x4.trans.shared.b16 {%0,%1,%2,%3}, [%4];"
                 : "=r"(r[0]), "=r"(r[1]), "=r"(r[2]), "=r"(r[3]) : "r"(addr));
}
// fp16 x fp16 -> fp32 accum (validated in R14)
__device__ __forceinline__ void mma_f16(float (&d)[4], const uint32_t (&a)[4],
                                        uint32_t b0, uint32_t b1) {
    asm volatile(
        "mma.sync.aligned.m16n8k16.row.col.f32.f16.f16.f32 "
        "{%0,%1,%2,%3},{%4,%5,%6,%7},{%8,%9},{%0,%1,%2,%3};"
        : "+f"(d[0]), "+f"(d[1]), "+f"(d[2]), "+f"(d[3])
        : "r"(a[0]), "r"(a[1]), "r"(a[2]), "r"(a[3]), "r"(b0), "r"(b1));
}
__device__ __forceinline__ uint32_t h2bits(__half2 v) {
    return *reinterpret_cast<uint32_t*>(&v);
}
// fp32 pair -> packed fp16 hi pair + fp16 residual pair
__device__ __forceinline__ void split2h(float a, float b, uint32_t& hi, uint32_t& lo) {
    __half ha = __float2half_rn(a);
    __half hb = __float2half_rn(b);
    hi = h2bits(__half2(ha, hb));
    lo = h2bits(__half2(__float2half_rn(a - __half2float(ha)),
                        __float2half_rn(b - __half2float(hb))));
}

// ---------------------------------------------------------------------------
// Converters
// ---------------------------------------------------------------------------
__global__ __launch_bounds__(256) void conv_split_h(   // fp32 -> fp16 hi/lo
    const float4* __restrict__ src,
    uint2* __restrict__ hi, uint2* __restrict__ lo, int n4)
{
    int i = blockIdx.x * 256 + threadIdx.x;
    if (i >= n4) return;
    float4 f = src[i];
    uint2 h, l;
    split2h(f.x, f.y, h.x, l.x);
    split2h(f.z, f.w, h.y, l.y);
    hi[i] = h;
    lo[i] = l;
}
__global__ __launch_bounds__(256) void conv_half(      // fp32 -> fp16 single
    const float4* __restrict__ src, uint2* __restrict__ dst, int n4)
{
    int i = blockIdx.x * 256 + threadIdx.x;
    if (i >= n4) return;
    float4 f = src[i];
    uint2 o;
    o.x = h2bits(__floats2half2_rn(f.x, f.y));
    o.y = h2bits(__floats2half2_rn(f.z, f.w));
    dst[i] = o;
}

// ---------------------------------------------------------------------------
// GEMM, fp16 asymmetric 2-term split (validated R14 structure):
//   C = (Ahi + Alo)_fp16 @ fp16(W)^T + bias
// CTA 128x128, BK=32, 256 thr. Stage = 3 tiles (Ahi, Alo, W), double-buffered.
// MODE 0: fp32 [m][n] -> outf.
// MODE 1: head-split fp16 hi/lo -> outh/outl (Q projection).
// MODE 2: head-split fp16 hi only -> outh (K, V projections).
// ---------------------------------------------------------------------------
#define TILE_B    10240          // bytes per 128x32 tile (stride-40 rows)
#define STAGE3_B  (3 * TILE_B)   // 30720
#define G3SMEM    (2 * STAGE3_B) // 61440 B

template <int MODE>
__global__ __launch_bounds__(256, 2) void gemm_f16(
    const unsigned short* __restrict__ Ahi,
    const unsigned short* __restrict__ Alo,
    const unsigned short* __restrict__ W,
    const float* __restrict__ bias,
    float* __restrict__ outf,
    unsigned short* __restrict__ outh,
    unsigned short* __restrict__ outl)
{
    extern __shared__ char smraw[];
    const uint32_t sbase = smem_u32(smraw);

    const int tid  = threadIdx.x;
    const int lane = tid & 31;
    const int wid  = tid >> 5;
    const int wm   = wid & 3;
    const int wn   = wid >> 2;
    const int m0   = blockIdx.y * 128;
    const int n0   = blockIdx.x * 128;

    float acc[2][8][4];
#pragma unroll
    for (int mt = 0; mt < 2; mt++)
#pragma unroll
        for (int nt = 0; nt < 8; nt++)
#pragma unroll
            for (int e = 0; e < 4; e++) acc[mt][nt][e] = 0.0f;

    auto load_stage = [&](int s, int k0) {
        const uint32_t st = sbase + (uint32_t)s * STAGE3_B;
#pragma unroll
        for (int t8 = 0; t8 < 6; t8++) {
            int c    = tid + t8 * 256;        // 0..1535
            int tile = c >> 9;                // 0..2
            int rem  = c & 511;
            int r    = rem >> 2;
            int kc   = (rem & 3) * 8;
            uint32_t dst = st + (uint32_t)tile * TILE_B + (uint32_t)(r * 40 + kc) * 2;
            const unsigned short* g;
            if (tile == 0)      g = Ahi + (size_t)(m0 + r) * 2048 + k0 + kc;
            else if (tile == 1) g = Alo + (size_t)(m0 + r) * 2048 + k0 + kc;
            else                g = W   + (size_t)(n0 + r) * 2048 + k0 + kc;
            CP_ASYNC16(dst, g);
        }
    };

    load_stage(0, 0);
    CP_COMMIT;

    const int NIT = 2048 / 32;
    for (int it = 0; it < NIT; it++) {
        const int s = it & 1;
        if (it + 1 < NIT) {
            load_stage(s ^ 1, (it + 1) * 32);
            CP_COMMIT;
            CP_WAIT(1);
        } else {
            CP_WAIT(0);
        }
        __syncthreads();

        const uint32_t st = sbase + (uint32_t)s * STAGE3_B;
#pragma unroll
        for (int ks = 0; ks < 2; ks++) {
            uint32_t aHi[2][4], aLo[2][4];
            const int arow = lane & 15;
            const int akof = ks * 16 + ((lane >> 4) << 3);
#pragma unroll
            for (int mt = 0; mt < 2; mt++) {
                uint32_t ad = st + (uint32_t)((wm * 32 + mt * 16 + arow) * 40 + akof) * 2;
                ldm_x4(aHi[mt], ad);
                ldm_x4(aLo[mt], ad + TILE_B);
            }
            const int brow = (lane & 7) + ((lane >> 4) << 3);
            const int bkof = ks * 16 + (((lane >> 3) & 1) << 3);
#pragma unroll
            for (int pr = 0; pr < 2; pr++) {
                uint32_t bW[2][4];
#pragma unroll
                for (int q = 0; q < 2; q++) {
                    int nt2 = pr * 2 + q;
                    uint32_t bd = st + 2 * TILE_B +
                        (uint32_t)((wn * 64 + nt2 * 16 + brow) * 40 + bkof) * 2;
                    ldm_x4(bW[q], bd);
                }
#pragma unroll
                for (int q = 0; q < 2; q++) {   // term 1: aHi * W
                    int nt2 = pr * 2 + q;
                    mma_f16(acc[0][2 * nt2],     aHi[0], bW[q][0], bW[q][1]);
                    mma_f16(acc[0][2 * nt2 + 1], aHi[0], bW[q][2], bW[q][3]);
                    mma_f16(acc[1][2 * nt2],     aHi[1], bW[q][0], bW[q][1]);
                    mma_f16(acc[1][2 * nt2 + 1], aHi[1], bW[q][2], bW[q][3]);
                }
#pragma unroll
                for (int q = 0; q < 2; q++) {   // term 2: aLo * W
                    int nt2 = pr * 2 + q;
                    mma_f16(acc[0][2 * nt2],     aLo[0], bW[q][0], bW[q][1]);
                    mma_f16(acc[0][2 * nt2 + 1], aLo[0], bW[q][2], bW[q][3]);
                    mma_f16(acc[1][2 * nt2],     aLo[1], bW[q][0], bW[q][1]);
                    mma_f16(acc[1][2 * nt2 + 1], aLo[1], bW[q][2], bW[q][3]);
                }
            }
        }
        __syncthreads();
    }

    // ---- epilogue ----
    const int gr = lane >> 2;
    const int c2 = (lane & 3) * 2;
#pragma unroll
    for (int mt = 0; mt < 2; mt++) {
#pragma unroll
        for (int nt = 0; nt < 8; nt++) {
            int m = m0 + wm * 32 + mt * 16 + gr;
            int n = n0 + wn * 64 + nt * 8 + c2;
            float b0 = bias[n], b1 = bias[n + 1];
            float f00 = acc[mt][nt][0] + b0, f01 = acc[mt][nt][1] + b1;
            float f10 = acc[mt][nt][2] + b0, f11 = acc[mt][nt][3] + b1;
            if (MODE == 0) {
                *reinterpret_cast<float2*>(&outf[(size_t)m * D_ + n])
                    = make_float2(f00, f01);
                *reinterpret_cast<float2*>(&outf[(size_t)(m + 8) * D_ + n])
                    = make_float2(f10, f11);
            } else {
                int b  = m >> 11, t = m & (T_ - 1);
                int h  = n >> 6,  hd = n & (HD_ - 1);
                size_t i0 = (((size_t)(b * H_ + h)) * T_ + t) * HD_ + hd;
                size_t i1 = (((size_t)(b * H_ + h)) * T_ + (t + 8)) * HD_ + hd;
                if (MODE == 1) {
                    uint32_t hi0, lo0, hi1, lo1;
                    split2h(f00, f01, hi0, lo0);
                    split2h(f10, f11, hi1, lo1);
                    *reinterpret_cast<uint32_t*>(&outh[i0]) = hi0;
                    *reinterpret_cast<uint32_t*>(&outl[i0]) = lo0;
                    *reinterpret_cast<uint32_t*>(&outh[i1]) = hi1;
                    *reinterpret_cast<uint32_t*>(&outl[i1]) = lo1;
                } else {  // MODE == 2: hi only
                    *reinterpret_cast<uint32_t*>(&outh[i0]) =
                        h2bits(__floats2half2_rn(f00, f01));
                    *reinterpret_cast<uint32_t*>(&outh[i1]) =
                        h2bits(__floats2half2_rn(f10, f11));
                }
            }
        }
    }
}

// ---------------------------------------------------------------------------
// Flash attention (causal), fp16 — R14 flash skeleton with:
// KV stage = 2 tiles (K, V single fp16), QK^T 2-term, PV 1-term.
// Grid (32, 64), 128 thr (4 warps). Br=Bc=64, HD=64.
// ---------------------------------------------------------------------------
#define FS        72
#define FKTILE_B  (64 * FS * 2)           // 9216 B per 64x64 tile
#define FQ_B      (2 * FKTILE_B)          // Qhi, Qlo
#define FSTG_B    (2 * FKTILE_B)          // K, V
#define FSMEM     (FQ_B + 2 * FSTG_B)     // 55296 B

__global__ __launch_bounds__(128, 2) void flash_f16(
    const unsigned short* __restrict__ qhi_g, const unsigned short* __restrict__ qlo_g,
    const unsigned short* __restrict__ k_g,   const unsigned short* __restrict__ v_g,
    unsigned short* __restrict__ chi, unsigned short* __restrict__ clo)
{
    extern __shared__ char fsm[];
    const uint32_t sb = smem_u32(fsm);
    const int tid  = threadIdx.x;
    const int lane = tid & 31;
    const int w    = tid >> 5;
    const int bh   = blockIdx.y;
    const int q0   = (gridDim.x - 1 - blockIdx.x) * 64;   // heavy tiles first
    const size_t hb = (size_t)bh * T_ * HD_;

#pragma unroll
    for (int m = 0; m < 2; m++) {
        const unsigned short* src = m ? qlo_g : qhi_g;
        uint32_t dstb = sb + (uint32_t)m * FKTILE_B;
#pragma unroll
        for (int i = 0; i < 4; i++) {
            int c = tid + i * 128;
            int r = c >> 3, ch = (c & 7) * 8;
            CP_ASYNC16(dstb + (uint32_t)(r * FS + ch) * 2,
                       src + hb + (size_t)(q0 + r) * HD_ + ch);
        }
    }
    CP_COMMIT;

    auto load_kv = [&](int s, int k0) {
        uint32_t st = sb + FQ_B + (uint32_t)s * FSTG_B;
        const unsigned short* srcs[2] = {k_g, v_g};
#pragma unroll
        for (int m = 0; m < 2; m++) {
#pragma unroll
            for (int i = 0; i < 4; i++) {
                int c = tid + i * 128;
                int r = c >> 3, ch = (c & 7) * 8;
                CP_ASYNC16(st + (uint32_t)m * FKTILE_B + (uint32_t)(r * FS + ch) * 2,
                           srcs[m] + hb + (size_t)(k0 + r) * HD_ + ch);
            }
        }
    };
    load_kv(0, 0);
    CP_COMMIT;
    CP_WAIT(1);            // Q done
    __syncthreads();

    uint32_t qh[4][4], ql[4][4];
    {
        int arow = lane & 15, akof = (lane >> 4) * 8;
#pragma unroll
        for (int kt = 0; kt < 4; kt++) {
            uint32_t ad = sb + (uint32_t)((16 * w + arow) * FS + kt * 16 + akof) * 2;
            ldm_x4(qh[kt], ad);
            ldm_x4(ql[kt], ad + FKTILE_B);
        }
    }

    float ctx[8][4];
#pragma unroll
    for (int nt = 0; nt < 8; nt++)
#pragma unroll
        for (int e = 0; e < 4; e++) ctx[nt][e] = 0.0f;
    float mrow0 = -1e30f, mrow1 = -1e30f, lrow0 = 0.0f, lrow1 = 0.0f;

    const int nkv = (q0 >> 6) + 1;
    const int gr  = lane >> 2;
    const int c2  = (lane & 3) * 2;
    const float scale = 0.125f;
    const int qg0 = q0 + 16 * w + gr;
    const int qg1 = qg0 + 8;

    for (int kt = 0; kt < nkv; kt++) {
        const int s = kt & 1;
        if (kt + 1 < nkv) {
            load_kv(s ^ 1, (kt + 1) * 64);
            CP_COMMIT;
            CP_WAIT(1);
        } else {
            CP_WAIT(0);
        }
        __syncthreads();
        const uint32_t st = sb + FQ_B + (uint32_t)s * FSTG_B;

        // ---- S = Q K^T (2-term: Qhi*K + Qlo*K) ----
        float sa[8][4];
#pragma unroll
        for (int nt = 0; nt < 8; nt++)
#pragma unroll
            for (int e = 0; e < 4; e++) sa[nt][e] = 0.0f;
        {
            const int brow = (lane & 7) + ((lane >> 4) << 3);
            const int bkof = ((lane >> 3) & 1) << 3;
#pragma unroll
            for (int k4 = 0; k4 < 4; k4++) {
                uint32_t bk4[4][4];
#pragma unroll
                for (int nt2 = 0; nt2 < 4; nt2++) {
                    uint32_t bd = st +
                        (uint32_t)((nt2 * 16 + brow) * FS + k4 * 16 + bkof) * 2;
                    ldm_x4(bk4[nt2], bd);
                }
#pragma unroll
                for (int nt2 = 0; nt2 < 4; nt2++) {
                    mma_f16(sa[2 * nt2],     qh[k4], bk4[nt2][0], bk4[nt2][1]);
                    mma_f16(sa[2 * nt2 + 1], qh[k4], bk4[nt2][2], bk4[nt2][3]);
                }
#pragma unroll
                for (int nt2 = 0; nt2 < 4; nt2++) {
                    mma_f16(sa[2 * nt2],     ql[k4], bk4[nt2][0], bk4[nt2][1]);
                    mma_f16(sa[2 * nt2 + 1], ql[k4], bk4[nt2][2], bk4[nt2][3]);
                }
            }
        }

        // ---- scale + causal mask (diag tile only) ----
        const bool diag = (kt == nkv - 1);
#pragma unroll
        for (int nt = 0; nt < 8; nt++) {
            int kg = kt * 64 + nt * 8 + c2;
            sa[nt][0] = (diag && kg     > qg0) ? -1e30f : sa[nt][0] * scale;
            sa[nt][1] = (diag && kg + 1 > qg0) ? -1e30f : sa[nt][1] * scale;
            sa[nt][2] = (diag && kg     > qg1) ? -1e30f : sa[nt][2] * scale;
            sa[nt][3] = (diag && kg + 1 > qg1) ? -1e30f : sa[nt][3] * scale;
        }

        // ---- online softmax ----
        float mx0 = -1e30f, mx1 = -1e30f;
#pragma unroll
        for (int nt = 0; nt < 8; nt++) {
            mx0 = fmaxf(mx0, fmaxf(sa[nt][0], sa[nt][1]));
            mx1 = fmaxf(mx1, fmaxf(sa[nt][2], sa[nt][3]));
        }
        mx0 = fmaxf(mx0, __shfl_xor_sync(0xffffffffu, mx0, 1));
        mx0 = fmaxf(mx0, __shfl_xor_sync(0xffffffffu, mx0, 2));
        mx1 = fmaxf(mx1, __shfl_xor_sync(0xffffffffu, mx1, 1));
        mx1 = fmaxf(mx1, __shfl_xor_sync(0xffffffffu, mx1, 2));
        float mn0 = fmaxf(mrow0, mx0), mn1 = fmaxf(mrow1, mx1);
        float al0 = __expf(mrow0 - mn0), al1 = __expf(mrow1 - mn1);
        mrow0 = mn0; mrow1 = mn1;
        float sum0 = 0.0f, sum1 = 0.0f;
#pragma unroll
        for (int nt = 0; nt < 8; nt++) {
            float p0 = __expf(sa[nt][0] - mn0);
            float p1 = __expf(sa[nt][1] - mn0);
            float p2 = __expf(sa[nt][2] - mn1);
            float p3 = __expf(sa[nt][3] - mn1);
            sa[nt][0] = p0; sa[nt][1] = p1; sa[nt][2] = p2; sa[nt][3] = p3;
            sum0 += p0 + p1; sum1 += p2 + p3;
        }
        sum0 += __shfl_xor_sync(0xffffffffu, sum0, 1);
        sum0 += __shfl_xor_sync(0xffffffffu, sum0, 2);
        sum1 += __shfl_xor_sync(0xffffffffu, sum1, 1);
        sum1 += __shfl_xor_sync(0xffffffffu, sum1, 2);
        lrow0 = lrow0 * al0 + sum0;
        lrow1 = lrow1 * al1 + sum1;
#pragma unroll
        for (int nt = 0; nt < 8; nt++) {
            ctx[nt][0] *= al0; ctx[nt][1] *= al0;
            ctx[nt][2] *= al1; ctx[nt][3] *= al1;
        }

        // ---- ctx += P V (1-term: fp16 P x fp16 V) ----
        {
            const int vrow = (lane & 7) + (((lane >> 3) & 1) << 3);
            const int vcol = (lane >> 4) << 3;
#pragma unroll
            for (int kt2 = 0; kt2 < 4; kt2++) {
                uint32_t pa[4];
                pa[0] = h2bits(__floats2half2_rn(sa[2 * kt2][0],     sa[2 * kt2][1]));
                pa[1] = h2bits(__floats2half2_rn(sa[2 * kt2][2],     sa[2 * kt2][3]));
                pa[2] = h2bits(__floats2half2_rn(sa[2 * kt2 + 1][0], sa[2 * kt2 + 1][1]));
                pa[3] = h2bits(__floats2half2_rn(sa[2 * kt2 + 1][2], sa[2 * kt2 + 1][3]));
                uint32_t v4[4][4];
#pragma unroll
                for (int dt = 0; dt < 4; dt++) {
                    uint32_t vd = st + FKTILE_B +
                        (uint32_t)((16 * kt2 + vrow) * FS + dt * 16 + vcol) * 2;
                    ldm_x4_t(v4[dt], vd);
                }
#pragma unroll
                for (int dt = 0; dt < 4; dt++) {
                    mma_f16(ctx[2 * dt],     pa, v4[dt][0], v4[dt][1]);
                    mma_f16(ctx[2 * dt + 1], pa, v4[dt][2], v4[dt][3]);
                }
            }
        }
        __syncthreads();
    }

    // ---- epilogue: normalize, emit ctx fp16 hi/lo split [b*T+t][h*HD+hd] ----
    const float il0 = 1.0f / lrow0, il1 = 1.0f / lrow1;
    const int b = bh / H_, h = bh % H_;
    const int t0 = q0 + 16 * w + gr, t1 = t0 + 8;
#pragma unroll
    for (int nt = 0; nt < 8; nt++) {
        int d = nt * 8 + c2;
        size_t i0 = ((size_t)(b * T_ + t0)) * D_ + h * HD_ + d;
        size_t i1 = ((size_t)(b * T_ + t1)) * D_ + h * HD_ + d;
        uint32_t hi0, lo0, hi1, lo1;
        split2h(ctx[nt][0] * il0, ctx[nt][1] * il0, hi0, lo0);
        split2h(ctx[nt][2] * il1, ctx[nt][3] * il1, hi1, lo1);
        *reinterpret_cast<uint32_t*>(&chi[i0]) = hi0;
        *reinterpret_cast<uint32_t*>(&clo[i0]) = lo0;
        *reinterpret_cast<uint32_t*>(&chi[i1]) = hi1;
        *reinterpret_cast<uint32_t*>(&clo[i1]) = lo1;
    }
}

// ---------------------------------------------------------------------------
// Launch
// ---------------------------------------------------------------------------
extern "C" void kernel_launch(void* const* d_in, const int* in_sizes, int n_in,
                              void* d_out, int out_size)
{
    const float* x  = (const float*)d_in[0];
    const float* Wq = (const float*)d_in[1];
    const float* bq = (const float*)d_in[2];
    const float* Wk = (const float*)d_in[3];
    const float* bk = (const float*)d_in[4];
    const float* Wv = (const float*)d_in[5];
    const float* bv = (const float*)d_in[6];
    const float* Wo = (const float*)d_in[7];
    const float* bo = (const float*)d_in[8];
    float* out = (float*)d_out;

    unsigned short *qhi, *qlo, *kp, *vp, *xa, *xb, *wa;
    cudaGetSymbolAddress((void**)&qhi, g_qhi);
    cudaGetSymbolAddress((void**)&qlo, g_qlo);
    cudaGetSymbolAddress((void**)&kp,  g_k);
    cudaGetSymbolAddress((void**)&vp,  g_v);
    cudaGetSymbolAddress((void**)&xa,  g_xa);
    cudaGetSymbolAddress((void**)&xb,  g_xb);
    cudaGetSymbolAddress((void**)&wa,  g_wa);

    cudaFuncSetAttribute(gemm_f16<0>,
                         cudaFuncAttributeMaxDynamicSharedMemorySize, G3SMEM);
    cudaFuncSetAttribute(gemm_f16<1>,
                         cudaFuncAttributeMaxDynamicSharedMemorySize, G3SMEM);
    cudaFuncSetAttribute(gemm_f16<2>,
                         cudaFuncAttributeMaxDynamicSharedMemorySize, G3SMEM);
    cudaFuncSetAttribute(flash_f16,
                         cudaFuncAttributeMaxDynamicSharedMemorySize, FSMEM);

    const int n4x = (int)(MD_ / 4);
    const int n4w = (D_ * D_) / 4;
    dim3 gthr(256);
    dim3 ggrid(D_ / 128, M_ / 128);   // (16, 32)
    dim3 fgrid(T_ / 64, B_ * H_);     // (32, 64)

    // X -> fp16 hi/lo split
    conv_split_h<<<(n4x + 255) / 256, 256>>>(
        (const float4*)x, (uint2*)xa, (uint2*)xb, n4x);

    // Q (hi/lo), K (hi only), V (hi only) projections
    conv_half<<<(n4w + 255) / 256, 256>>>((const float4*)Wq, (uint2*)wa, n4w);
    gemm_f16<1><<<ggrid, gthr, G3SMEM>>>(xa, xb, wa, bq, nullptr, qhi, qlo);

    conv_half<<<(n4w + 255) / 256, 256>>>((const float4*)Wk, (uint2*)wa, n4w);
    gemm_f16<2><<<ggrid, gthr, G3SMEM>>>(xa, xb, wa, bk, nullptr, kp, nullptr);

    conv_half<<<(n4w + 255) / 256, 256>>>((const float4*)Wv, (uint2*)wa, n4w);
    gemm_f16<2><<<ggrid, gthr, G3SMEM>>>(xa, xb, wa, bv, nullptr, vp, nullptr);

    // Flash attention; ctx fp16 hi/lo into xa/xb
    flash_f16<<<fgrid, 128, FSMEM>>>(qhi, qlo, kp, vp, xa, xb);

    // O projection (fp32 out)
    conv_half<<<(n4w + 255) / 256, 256>>>((const float4*)Wo, (uint2*)wa, n4w);
    gemm_f16<0><<<ggrid, gthr, G3SMEM>>>(xa, xb, wa, bo, out, nullptr, nullptr);

    (void)in_sizes; (void)n_in; (void)out_size;
}